// round 6
// baseline (speedup 1.0000x reference)
#include <cuda_runtime.h>
#include <math.h>

// Problem constants (fixed by the reference)
#define NN    10000
#define EE    160000
#define CC    16
#define CHW   1024       // C*H*W
#define DE    64         // edge feature dim
#define HID   128        // hidden dim
#define NSEG  (2 * NN)   // (node, dir) segments; dir 0 = out (r<c), 1 = in (r>c)
#define NSCANB ((NSEG + 1023) / 1024)   // 20 scan blocks

// ---------------------------------------------------------------------------
// Scratch (__device__ globals; no allocations allowed)
// ---------------------------------------------------------------------------
__device__ float g_sum_in [NN];
__device__ float g_sum_out[NN];
__device__ float g_exp[EE];
__device__ int   g_row[EE];
__device__ int   g_col[EE];
__device__ int   g_is64;
__device__ int   g_cnt[NSEG];
__device__ int   g_off[NSEG + 1];
__device__ int   g_pos[NSEG];
__device__ int   g_bsum[NSCANB];
__device__ int   g_scol[EE];       // col of sorted edge
__device__ float g_sw  [EE];       // softmax weight of sorted edge

// ---------------------------------------------------------------------------
// f32x2 packed helpers (sm_100+): 2 fp32 FMAs per issue slot.
// ---------------------------------------------------------------------------
__device__ __forceinline__ unsigned long long ffma2(unsigned long long a,
                                                    unsigned long long b,
                                                    unsigned long long c) {
    unsigned long long d;
    asm("fma.rn.f32x2 %0, %1, %2, %3;" : "=l"(d) : "l"(a), "l"(b), "l"(c));
    return d;
}
__device__ __forceinline__ unsigned long long pack2(float a) {
    unsigned long long r;
    unsigned int u = __float_as_uint(a);
    asm("mov.b64 %0, {%1, %1};" : "=l"(r) : "r"(u));
    return r;
}
union U64F2 { unsigned long long u; float2 f; };

// ---------------------------------------------------------------------------
// Kernel 1: zero accumulators + (block 0) detect int64 vs int32 edge_index.
// ---------------------------------------------------------------------------
__global__ void zero_kernel(const int* __restrict__ v32) {
    int i = blockIdx.x * blockDim.x + threadIdx.x;
    if (i < NSEG) g_cnt[i] = 0;
    if (i < NN) { g_sum_in[i] = 0.f; g_sum_out[i] = 0.f; }
    if (blockIdx.x == 0 && threadIdx.x < 32) {
        int t = threadIdx.x;
        int nz = 0;
#pragma unroll
        for (int q = 0; q < 4; q++)
            nz |= (v32[2 * (t + q * 32) + 1] != 0);
#pragma unroll
        for (int s = 16; s > 0; s >>= 1)
            nz |= __shfl_xor_sync(0xffffffffu, nz, s);
        if (t == 0) g_is64 = nz ? 0 : 1;
    }
}

// ---------------------------------------------------------------------------
// Kernel 2: decode edge_index + segment histogram (merged)
// ---------------------------------------------------------------------------
__global__ void decode_kernel(const int* __restrict__ v32) {
    int e = blockIdx.x * blockDim.x + threadIdx.x;
    if (e >= EE) return;
    int r, c;
    if (g_is64) { r = v32[2 * e]; c = v32[2 * (EE + e)]; }
    else        { r = v32[e];     c = v32[EE + e]; }
    g_row[e] = r;
    g_col[e] = c;
    if (r != c) atomicAdd(&g_cnt[r * 2 + ((r < c) ? 0 : 1)], 1);
}

// ---------------------------------------------------------------------------
// Kernel 3a: per-block local scan + block sums
// ---------------------------------------------------------------------------
__global__ void scanA_kernel() {      // NSCANB blocks x 1024
    __shared__ int wsum[32];
    const int t = threadIdx.x, lane = t & 31, wid = t >> 5;
    const int idx = blockIdx.x * 1024 + t;
    int v = (idx < NSEG) ? g_cnt[idx] : 0;
    int s = v;
#pragma unroll
    for (int off = 1; off < 32; off <<= 1) {
        int n = __shfl_up_sync(0xffffffffu, s, off);
        if (lane >= off) s += n;
    }
    if (lane == 31) wsum[wid] = s;
    __syncthreads();
    if (wid == 0) {
        int w = wsum[lane];
#pragma unroll
        for (int off = 1; off < 32; off <<= 1) {
            int n = __shfl_up_sync(0xffffffffu, w, off);
            if (lane >= off) w += n;
        }
        wsum[lane] = w;
    }
    __syncthreads();
    int incl = s + ((wid > 0) ? wsum[wid - 1] : 0);
    if (idx < NSEG) g_off[idx] = incl - v;       // local exclusive
    if (t == 1023) g_bsum[blockIdx.x] = incl;    // block total
}

// ---------------------------------------------------------------------------
// Kernel 3b: apply block offsets (each block re-scans the 20 block sums)
// ---------------------------------------------------------------------------
__global__ void scanC_kernel() {
    __shared__ int s_pre[NSCANB + 1];
    const int t = threadIdx.x;
    if (t < 32) {
        int v = (t < NSCANB) ? g_bsum[t] : 0;
        int s = v;
#pragma unroll
        for (int off = 1; off < 32; off <<= 1) {
            int n = __shfl_up_sync(0xffffffffu, s, off);
            if (t >= off) s += n;
        }
        if (t < NSCANB) s_pre[t] = s - v;       // exclusive
        if (t == 31)    s_pre[NSCANB] = s;      // grand total
    }
    __syncthreads();
    int idx = blockIdx.x * blockDim.x + t;
    if (idx < NSEG) {
        int o = g_off[idx] + s_pre[idx >> 10];
        g_off[idx] = o;
        g_pos[idx] = o;
    }
    if (idx == 0) g_off[NSEG] = s_pre[NSCANB];
}

// ---------------------------------------------------------------------------
// Kernel 4: edge MLP (f32x2 packed) -> logits, exp, softmax denominators.
// Launched BEFORE the CSR fill so fill can finalize softmax weights.
// ---------------------------------------------------------------------------
#define EPB 256
#define EA_STRIDE 68
#define MLP_SMEM_FLOATS (8464 + EPB * EA_STRIDE)
#define MLP_SMEM_BYTES  (MLP_SMEM_FLOATS * 4)

extern __shared__ float smem[];

__global__ void __launch_bounds__(128)
mlp_kernel(const float* __restrict__ edge_attr,
           const float* __restrict__ W1,
           const float* __restrict__ b1,
           const float* __restrict__ W2,
           const float* __restrict__ b2,
           float* __restrict__ logits,
           int write_logits) {
    float* W1s = smem;              // [64][128]
    float* b1s = smem + 8192;       // 128
    float* W2s = smem + 8320;       // 128
    float* b2s = smem + 8448;       // 1 (pad to 8464 for 16B alignment)
    float* eas = smem + 8464;       // [256][68]

    const int t = threadIdx.x;

    for (int i = t; i < 8192; i += 128) W1s[i] = W1[i];
    if (t < 128) { b1s[t] = b1[t]; W2s[t] = W2[t]; }
    if (t == 0)  b2s[0] = b2[0];

    const float4* ea4 = reinterpret_cast<const float4*>(
        edge_attr + (size_t)blockIdx.x * EPB * DE);
    for (int i = t; i < EPB * DE / 4; i += 128) {
        float4 v = ea4[i];
        int edge = i >> 4;
        int k4   = i & 15;
        reinterpret_cast<float4*>(&eas[edge * EA_STRIDE])[k4] = v;
    }
    __syncthreads();

    float logit0 = b2s[0];
    float logit1 = b2s[0];
    const float4* ea0 = reinterpret_cast<const float4*>(&eas[t * EA_STRIDE]);
    const float4* ea1 = reinterpret_cast<const float4*>(
        &eas[(t + 128) * EA_STRIDE]);

#pragma unroll
    for (int j0 = 0; j0 < HID; j0 += 32) {
        unsigned long long acc0[16], acc1[16];
        const unsigned long long* b1p =
            reinterpret_cast<const unsigned long long*>(&b1s[j0]);
#pragma unroll
        for (int m = 0; m < 16; m++) { acc0[m] = b1p[m]; acc1[m] = b1p[m]; }

#pragma unroll 2
        for (int k4 = 0; k4 < 16; k4++) {
            float4 a0 = ea0[k4];          // LDS.128, conflict-free
            float4 a1 = ea1[k4];
            float a0v[4] = {a0.x, a0.y, a0.z, a0.w};
            float a1v[4] = {a1.x, a1.y, a1.z, a1.w};
#pragma unroll
            for (int kk = 0; kk < 4; kk++) {
                unsigned long long A0 = pack2(a0v[kk]);
                unsigned long long A1 = pack2(a1v[kk]);
                const ulonglong2* w2 = reinterpret_cast<const ulonglong2*>(
                    &W1s[(k4 * 4 + kk) * HID + j0]);
#pragma unroll
                for (int m = 0; m < 8; m++) {
                    ulonglong2 w = w2[m];   // broadcast LDS.128
                    acc0[2*m]   = ffma2(A0, w.x, acc0[2*m]);
                    acc0[2*m+1] = ffma2(A0, w.y, acc0[2*m+1]);
                    acc1[2*m]   = ffma2(A1, w.x, acc1[2*m]);
                    acc1[2*m+1] = ffma2(A1, w.y, acc1[2*m+1]);
                }
            }
        }
#pragma unroll
        for (int m = 0; m < 16; m++) {
            U64F2 c0; c0.u = acc0[m];
            U64F2 c1; c1.u = acc1[m];
            float w2a = W2s[j0 + 2*m];
            float w2b = W2s[j0 + 2*m + 1];
            logit0 += fmaxf(c0.f.x, 0.f) * w2a + fmaxf(c0.f.y, 0.f) * w2b;
            logit1 += fmaxf(c1.f.x, 0.f) * w2a + fmaxf(c1.f.y, 0.f) * w2b;
        }
    }

    const int e0 = blockIdx.x * EPB + t;
    const int e1 = e0 + 128;
    {
        if (write_logits) logits[e0] = logit0;
        float ex = expf(logit0);
        g_exp[e0] = ex;
        int r = g_row[e0], c = g_col[e0];
        if (r < c)      atomicAdd(&g_sum_out[r], ex);
        else if (r > c) atomicAdd(&g_sum_in[r],  ex);
    }
    {
        if (write_logits) logits[e1] = logit1;
        float ex = expf(logit1);
        g_exp[e1] = ex;
        int r = g_row[e1], c = g_col[e1];
        if (r < c)      atomicAdd(&g_sum_out[r], ex);
        else if (r > c) atomicAdd(&g_sum_in[r],  ex);
    }
}

// ---------------------------------------------------------------------------
// Kernel 5: fill CSR lists with final softmax weights (sums ready post-MLP)
// ---------------------------------------------------------------------------
__global__ void fill_kernel() {
    int e = blockIdx.x * blockDim.x + threadIdx.x;
    if (e >= EE) return;
    int r = g_row[e], c = g_col[e];
    if (r == c) return;
    int dirin = (r > c);
    int seg = r * 2 + dirin;
    int pos = atomicAdd(&g_pos[seg], 1);
    float sum = dirin ? g_sum_in[r] : g_sum_out[r];
    g_scol[pos] = c;
    g_sw[pos]   = g_exp[e] / fmaxf(sum, 1e-30f);
}

// ---------------------------------------------------------------------------
// Kernel 6: fused gather-aggregate + 1x1 conv. One block per node.
// 4-wide unrolled edge gather for memory-level parallelism.
// ---------------------------------------------------------------------------
#define ECHUNK 128

__global__ void __launch_bounds__(256)
fused_kernel(const float* __restrict__ x,
             const float* __restrict__ Wn,
             const float* __restrict__ bn,
             float* __restrict__ out) {
    __shared__ float s_fo[CHW];      // flow_out
    __shared__ float s_fi[CHW];      // flow_in
    __shared__ float WsT[48 * 16];   // WsT[cc][o] = Wn[o*48+cc]
    __shared__ float bs[16];
    __shared__ int   s_ec[ECHUNK];
    __shared__ float s_ew[ECHUNK];

    const int n = blockIdx.x;
    const int t = threadIdx.x;

    for (int i = t; i < 768; i += 256) {
        int o = i / 48, cc = i % 48;
        WsT[cc * 16 + o] = Wn[i];
    }
    if (t < 16) bs[t] = bn[t];

    const int off0 = g_off[2 * n];
    const int off1 = g_off[2 * n + 1];
    const int off2 = g_off[2 * n + 2];

    const float4* x4 = reinterpret_cast<const float4*>(x);

    float4 accO = make_float4(0.f, 0.f, 0.f, 0.f);
    float4 accI = make_float4(0.f, 0.f, 0.f, 0.f);

#pragma unroll 1
    for (int dir = 0; dir < 2; dir++) {
        const int lo = dir ? off1 : off0;
        const int hi = dir ? off2 : off1;
        float4 acc = make_float4(0.f, 0.f, 0.f, 0.f);

        for (int base = lo; base < hi; base += ECHUNK) {
            int m = min(ECHUNK, hi - base);
            __syncthreads();
            for (int j = t; j < m; j += 256) {
                s_ec[j] = g_scol[base + j];
                s_ew[j] = g_sw[base + j];
            }
            __syncthreads();

            int j = 0;
            for (; j + 4 <= m; j += 4) {
                float w0 = s_ew[j],   w1 = s_ew[j+1];
                float w2 = s_ew[j+2], w3 = s_ew[j+3];
                float4 v0 = __ldg(&x4[(size_t)s_ec[j]   * 256 + t]);
                float4 v1 = __ldg(&x4[(size_t)s_ec[j+1] * 256 + t]);
                float4 v2 = __ldg(&x4[(size_t)s_ec[j+2] * 256 + t]);
                float4 v3 = __ldg(&x4[(size_t)s_ec[j+3] * 256 + t]);
                acc.x += w0*v0.x + w1*v1.x + w2*v2.x + w3*v3.x;
                acc.y += w0*v0.y + w1*v1.y + w2*v2.y + w3*v3.y;
                acc.z += w0*v0.z + w1*v1.z + w2*v2.z + w3*v3.z;
                acc.w += w0*v0.w + w1*v1.w + w2*v2.w + w3*v3.w;
            }
            for (; j < m; j++) {
                float w = s_ew[j];
                float4 v = __ldg(&x4[(size_t)s_ec[j] * 256 + t]);
                acc.x += w*v.x; acc.y += w*v.y;
                acc.z += w*v.z; acc.w += w*v.w;
            }
        }
        if (dir) accI = acc; else accO = acc;
    }

    __syncthreads();
    reinterpret_cast<float4*>(s_fo)[t] = accO;
    reinterpret_cast<float4*>(s_fi)[t] = accI;
    __syncthreads();

    const int hw = t & 63;
    const int og = t >> 6;

    float acc[4];
#pragma unroll
    for (int j = 0; j < 4; j++) acc[j] = bs[og * 4 + j];

    const float* xb = x + (size_t)n * CHW;
#pragma unroll 4
    for (int cc = 0; cc < 16; cc++) {
        float vx = __ldg(&xb[cc * 64 + hw]);
        float vi = s_fi[cc * 64 + hw];
        float vo = s_fo[cc * 64 + hw];
        float4 wx = reinterpret_cast<const float4*>(&WsT[(cc)      * 16])[og];
        float4 wi = reinterpret_cast<const float4*>(&WsT[(16 + cc) * 16])[og];
        float4 wo = reinterpret_cast<const float4*>(&WsT[(32 + cc) * 16])[og];
        acc[0] += vx * wx.x + vi * wi.x + vo * wo.x;
        acc[1] += vx * wx.y + vi * wi.y + vo * wo.y;
        acc[2] += vx * wx.z + vi * wi.z + vo * wo.z;
        acc[3] += vx * wx.w + vi * wi.w + vo * wo.w;
    }

    float* ob = out + (size_t)n * CHW;
#pragma unroll
    for (int j = 0; j < 4; j++)
        ob[(og * 4 + j) * 64 + hw] = acc[j];
}

// ---------------------------------------------------------------------------
// Launch (default stream; sequentially ordered; graph-capturable)
// MLP is the 4th launch (depends only on zero+decode) so ncu samples it.
// ---------------------------------------------------------------------------
extern "C" void kernel_launch(void* const* d_in, const int* in_sizes, int n_in,
                              void* d_out, int out_size) {
    const float* x         = (const float*)d_in[0];
    const float* edge_attr = (const float*)d_in[1];
    const float* W1        = (const float*)d_in[2];
    const float* b1        = (const float*)d_in[3];
    const float* W2        = (const float*)d_in[4];
    const float* b2        = (const float*)d_in[5];
    const float* Wn        = (const float*)d_in[6];
    const float* bn        = (const float*)d_in[7];
    const int*   ei32      = (const int*)d_in[8];

    float* out    = (float*)d_out;
    const int write_logits = (out_size >= NN * CHW + EE);
    float* logits = out + (size_t)NN * CHW;

    cudaFuncSetAttribute(mlp_kernel,
                         cudaFuncAttributeMaxDynamicSharedMemorySize,
                         MLP_SMEM_BYTES);

    const int EB = (EE + 255) / 256;

    zero_kernel<<<(NSEG + 255) / 256, 256>>>(ei32);
    decode_kernel<<<EB, 256>>>(ei32);
    scanA_kernel<<<NSCANB, 1024>>>();
    mlp_kernel<<<EE / EPB, 128, MLP_SMEM_BYTES>>>(edge_attr, W1, b1, W2, b2,
                                                  logits, write_logits);
    scanC_kernel<<<(NSEG + 255) / 256, 256>>>();
    fill_kernel<<<EB, 256>>>();
    fused_kernel<<<NN, 256>>>(x, Wn, bn, out);
}